// round 17
// baseline (speedup 1.0000x reference)
#include <cuda_runtime.h>
#include <math.h>
#include <cstdint>

// Fixed shape: query_len = key_len = 2048, 8 fp32 channels, TRUNC = 200.
#define QL 2048
#define KL 2048
#define NT 201              // distinct T values 0..200 (T>200 -> T=0 vector)
#define THREADS 256
#define CPIX 1024           // const staging buffer: 1024 px = 32 KB per copy
#define NCONST 512          // const CTAs, each covers 4 rows' const regions
#define ROWS_PER_CONST 4

__device__ __forceinline__ uint32_t smem_u32(const void* p) {
    uint32_t a;
    asm("{ .reg .u64 t; cvta.to.shared.u64 t, %1; cvt.u32.u64 %0, t; }"
        : "=r"(a) : "l"(p));
    return a;
}

__device__ __forceinline__ void bulk_s2g(float4* g, uint32_t s, int bytes) {
    asm volatile("cp.async.bulk.global.shared::cta.bulk_group [%0], [%1], %2;"
                 :: "l"(g), "r"(s), "r"(bytes) : "memory");
}

// Role-split grid (R16 was latency-bound on CTA prologues, all pipes ~50-65%):
//  - blocks [0, NCONST): const CTAs. One 32 KB const-buffer stage, then all
//    const-region copies for 4 rows (~210 KB each, 32 KB chunks), one drain.
//    They carry 77% of all bytes with only 512 prologues, and lead the grid
//    so the longest CTAs start first.
//  - blocks [NCONST, NCONST+QL): band CTAs, one per row. No const buffer:
//    ~200 cyc of transcendentals + direct scatter (band = LUT mirrored
//    around j==i) + one <=12.8 KB copy. Tiny; they fill scheduling gaps.
__global__ __launch_bounds__(THREADS) void fill_split_kernel(
    const float* __restrict__ eta, const float* __restrict__ nu,
    const float* __restrict__ theta, float4* __restrict__ out)
{
    __shared__ __align__(16) float4 sbuf[CPIX * 2];   // 32 KB (both roles)

    const int tid = threadIdx.x;
    const int bid = blockIdx.x;

    const float4 farA = make_float4(1.f, 1.f, 0.f, 0.f);
    const float4 farB = make_float4(1.f, 1.f, 1.f, 0.f);

    if (bid < NCONST) {
        // ================= const CTA =================
        // Stage 32 KB constant pattern with all 8 warps (8 STS.128/lane).
#pragma unroll
        for (int k = 0; k < (CPIX * 2) / THREADS; k++) {
            int f = tid + k * THREADS;
            sbuf[f] = (f & 1) ? farB : farA;
        }
        __syncthreads();

        if (tid == 0) {
            asm volatile("fence.proxy.async.shared::cta;" ::: "memory");
            const uint32_t cb = smem_u32(sbuf);
#pragma unroll
            for (int r = 0; r < ROWS_PER_CONST; r++) {
                const int i = bid * ROWS_PER_CONST + r;
                const int lo = (i - 200 > 0) ? i - 200 : 0;
                const int hi = (i + 200 < KL - 1) ? i + 200 : KL - 1;
                float4* gp = out + (size_t)i * (2 * KL);

                int rem = lo, off = 0;                 // left const [0, lo)
                while (rem > 0) {
                    int n = (rem < CPIX) ? rem : CPIX;
                    bulk_s2g(gp + 2 * off, cb, n * 32);
                    off += n; rem -= n;
                }
                rem = (KL - 1) - hi; off = hi + 1;     // right const (hi, KL)
                while (rem > 0) {
                    int n = (rem < CPIX) ? rem : CPIX;
                    bulk_s2g(gp + 2 * off, cb, n * 32);
                    off += n; rem -= n;
                }
            }
            asm volatile("cp.async.bulk.commit_group;" ::: "memory");
            asm volatile("cp.async.bulk.wait_group.read 0;" ::: "memory");
        }
        return;
    }

    // ================= band CTA (one per row) =================
    const int i  = bid - NCONST;
    const int lo = (i - 200 > 0) ? i - 200 : 0;
    const int hi = (i + 200 < KL - 1) ? i + 200 : KL - 1;

    if (tid < NT) {
        // Compute entry t = |i-j|, scatter to j = i-t and j = i+t.
        // (fp32 + __powf; rel_err ~3.4e-9 measured R14-R16)
        const int t = tid;
        float lambda = tanhf(eta[0]);
        float gamma  = 1.0f / (1.0f + expf(-nu[0]));
        float th     = theta[0];
        float T      = (float)t;

        float gT = __powf(gamma, T);
        float s, c;  sincosf(T * th, &s, &c);
        float v0 = gT * c;            // ch0, ch1
        float v2 = gT * s;            // ch2, ch3

        float L2d = (t % 2  == 0) ? T * 0.5f    : 0.0f;
        float L4d = (t % 4  == 0) ? T * 0.25f   : 0.0f;
        float L8d = (t % 8  == 0) ? T * 0.125f  : 0.0f;
        float L16 = (t % 16 == 0) ? T * 0.0625f : 0.0f;

        float v4 = __powf(lambda, L2d);                 // ch4
        float v5 = __powf(lambda, L4d);                 // ch5
        float s8, c8;   sincosf(L8d * th, &s8, &c8);
        float s16, c16; sincosf(L16 * th, &s16, &c16);
        float v6 = __powf(gamma, L8d) * c8;             // ch6
        float v7 = __powf(gamma, L16) * s16;            // ch7

        const float4 a = make_float4(v0, v0, v2, v2);
        const float4 b = make_float4(v4, v5, v6, v7);

        int j = i - t;                                  // left mirror
        if (j >= lo) {
            int k = j - lo;
            sbuf[2 * k]     = a;
            sbuf[2 * k + 1] = b;
        }
        j = i + t;                                      // right mirror
        if (t > 0 && j <= hi) {
            int k = j - lo;
            sbuf[2 * k]     = a;
            sbuf[2 * k + 1] = b;
        }
    }
    __syncthreads();

    if (tid == 0) {
        asm volatile("fence.proxy.async.shared::cta;" ::: "memory");
        const int npix = hi - lo + 1;                   // <= 401
        float4* gp = out + ((size_t)i * KL + lo) * 2;
        bulk_s2g(gp, smem_u32(sbuf), npix * 32);
        asm volatile("cp.async.bulk.commit_group;" ::: "memory");
        asm volatile("cp.async.bulk.wait_group.read 0;" ::: "memory");
    }
}

extern "C" void kernel_launch(void* const* d_in, const int* in_sizes, int n_in,
                              void* d_out, int out_size) {
    const float* eta   = (const float*)d_in[0];
    const float* nu    = (const float*)d_in[1];
    const float* theta = (const float*)d_in[2];

    fill_split_kernel<<<NCONST + QL, THREADS>>>(eta, nu, theta, (float4*)d_out);
}